// round 16
// baseline (speedup 1.0000x reference)
#include <cuda_runtime.h>
#include <cuda_fp16.h>
#include <math.h>
#include <stdint.h>

// ---------------- problem constants ----------------
#define DD    512
#define KC    1024
#define QL    8
#define NTOK  16384
#define MTOK  64                   // tokens per CTA
#define NTL   128                  // codes per N-tile
#define NITER 128                  // 8 ntiles * 16 chunks
#define NTHR  256                  // 8 warps
#define NCAND 32                   // approx candidates kept per token
#define NRES  8                    // exact-rescored candidates per token

#define IDXOFF ((size_t)NTOK * DD)
#define SCLOFF (IDXOFF + (size_t)NTOK * QL)

// ---------------- smem layout (bytes) ----------------
// B stages: [128 rows][80B] x 3
#define RSTRB  80u
#define STG_SZ 10240u
#define NSTG   3
#define OF_CSQ 30720u              // 4096
#define OF_RSQ 34816u              // 256 (64 floats, persistent)
#define OF_A   35072u              // 8 super-chunks x 64 rows x 144B = 73728
#define ASC_SZ 9216u               // 64*144
#define SMEM_TOT 108800u
// phase-2 scratch aliases B-stage region [0, 30720)
#define OF_CV   0u                 // 8192
#define OF_CI   8192u              // 8192
#define OF_SEL  16384u             // 2048
#define OF_DOTP 18432u             // 8192
#define OF_WIDX 26624u             // 256
#define OF_RSQP 26880u             // 1024

// ---------------- device scratch (static; no cudaMalloc) ----------------
__device__ float   g_csq[QL * KC];
__device__ int     g_cnt[QL * KC];
__device__ double  g_commit[QL];
__device__ float   g_res [(size_t)NTOK * DD];
__device__ __half  g_cbh [(size_t)QL * KC * DD]; // fp16 codebook

// ---------------- helpers ----------------
__device__ __forceinline__ uint32_t smem_u32(const void* p) {
    uint32_t a;
    asm("{ .reg .u64 t; cvta.to.shared.u64 t, %1; cvt.u32.u64 %0, t; }"
        : "=r"(a) : "l"(p));
    return a;
}
__device__ __forceinline__ void cpa16(uint32_t dst, const void* src) {
    asm volatile("cp.async.cg.shared.global [%0], [%1], 16;" :: "r"(dst), "l"(src));
}
#define CP_COMMIT() asm volatile("cp.async.commit_group;" ::: "memory")
#define CP_WAIT2()  asm volatile("cp.async.wait_group 2;" ::: "memory")
#define CP_WAIT1()  asm volatile("cp.async.wait_group 1;" ::: "memory")
#define CP_WAIT0()  asm volatile("cp.async.wait_group 0;" ::: "memory")

#define LDSM4(r0, r1, r2, r3, a)                                               \
    asm volatile("ldmatrix.sync.aligned.m8n8.x4.shared.b16 {%0,%1,%2,%3}, [%4];" \
                 : "=r"(r0), "=r"(r1), "=r"(r2), "=r"(r3) : "r"(a))

#define MMA_FP16(c, a0, a1, a2, a3, b0, b1)                                    \
    asm volatile("mma.sync.aligned.m16n8k16.row.col.f32.f16.f16.f32 "          \
                 "{%0,%1,%2,%3}, {%4,%5,%6,%7}, {%8,%9}, {%0,%1,%2,%3};"       \
                 : "+f"((c)[0]), "+f"((c)[1]), "+f"((c)[2]), "+f"((c)[3])      \
                 : "r"(a0), "r"(a1), "r"(a2), "r"(a3), "r"(b0), "r"(b1))

// sorted top-4 insert (v0<=v1<=v2<=v3); strict < keeps earliest on equal
#define TOP4_INS(v0,i0,v1,i1,v2,i2,v3,i3,d,c) do {                             \
    if ((d) < (v3)) {                                                          \
        if ((d) < (v2)) { v3 = v2; i3 = i2;                                    \
            if ((d) < (v1)) { v2 = v1; i2 = i1;                                \
                if ((d) < (v0)) { v1 = v0; i1 = i0; v0 = (d); i0 = (c); }      \
                else            { v1 = (d); i1 = (c); } }                      \
            else { v2 = (d); i2 = (c); } }                                     \
        else { v3 = (d); i3 = (c); } }                                         \
} while (0)

// ---------------------------------------------------------------------------
// prep: csq via coalesced 4-thread/row partials, zero stats
// ---------------------------------------------------------------------------
__global__ void rvq_prep(const float* __restrict__ cb) {
    __shared__ float pp[4 * 64];
    const int tid  = threadIdx.x;
    const int tsub = tid & 3, tloc = tid >> 2, dbase = tsub * 128;
    const int row  = blockIdx.x * 64 + tloc;
    const float* c = cb + (size_t)row * DD + dbase;
    float s = 0.f;
    #pragma unroll 4
    for (int j = 0; j < 128; j += 4) {
        float4 v = *(const float4*)(c + j);
        s += v.x * v.x; s += v.y * v.y; s += v.z * v.z; s += v.w * v.w;
    }
    pp[tsub * 64 + tloc] = s;
    __syncthreads();
    if (tid < 64)
        g_csq[blockIdx.x * 64 + tid] =
            ((pp[tid] + pp[64 + tid]) + pp[128 + tid]) + pp[192 + tid];
    if (tid < 64) g_cnt[blockIdx.x * 64 + tid] = 0;
    else if (blockIdx.x == 0 && tid >= 64 && (tid - 64) < QL)
        g_commit[tid - 64] = 0.0;
}

// codebook fp32 -> fp16
__global__ void rvq_cbconv(const float* __restrict__ cb) {
    size_t i = ((size_t)blockIdx.x * blockDim.x + threadIdx.x) * 4;
    if (i >= (size_t)QL * KC * DD) return;
    float4 v = *(const float4*)(cb + i);
    *(__half2*)(g_cbh + i)     = __floats2half2_rn(v.x, v.y);
    *(__half2*)(g_cbh + i + 2) = __floats2half2_rn(v.z, v.w);
}

// ---------------------------------------------------------------------------
// persistent kernel: all 8 levels in one launch. Per level: fp16 nomination
// GEMM (A resident in smem, B streamed) -> top-4 per lane-partition ->
// approx top-8 -> EXACT fp32 rescore (proven chain) -> residual update.
// ---------------------------------------------------------------------------
__global__ void __launch_bounds__(NTHR, 2)
rvq_persist(const float* __restrict__ x, const float* __restrict__ cb,
            float* __restrict__ out) {
    extern __shared__ char sm[];
    const uint32_t sb = smem_u32(sm);
    float* csq_sm = (float*)(sm + OF_CSQ);
    float* RSQ    = (float*)(sm + OF_RSQ);

    const int tid  = threadIdx.x;
    const int wid  = tid >> 5;
    const int lane = tid & 31;
    const int wm   = wid & 3;        // row group (4 x 16 rows)
    const int wn   = wid >> 2;       // code half within ntile
    const int tok0 = blockIdx.x * MTOK;

    const int tsub = tid & 3, tloc = tid >> 2, dbase = tsub * 128;
    const int tok  = tok0 + tloc;

    // ---- init: x -> A smem (fp16, super-chunk layout) + rsq
    {
        const float* xp = x + (size_t)tok * DD + dbase;
        float* RSQP = (float*)(sm + OF_RSQP);
        float s = 0.f;
        #pragma unroll 4
        for (int j = 0; j < 128; j += 4) {
            float4 v = *(const float4*)(xp + j);
            s += v.x * v.x; s += v.y * v.y; s += v.z * v.z; s += v.w * v.w;
            char* ap = sm + OF_A + (uint32_t)(tsub * 2 + (j >> 6)) * ASC_SZ
                       + (uint32_t)tloc * 144u + (uint32_t)(j & 63) * 2u;
            *(__half2*)ap       = __floats2half2_rn(v.x, v.y);
            *(__half2*)(ap + 4) = __floats2half2_rn(v.z, v.w);
        }
        RSQP[tsub * 64 + tloc] = s;
        __syncthreads();
        if (tid < 64)
            RSQ[tid] = ((RSQP[tid] + RSQP[64 + tid]) + RSQP[128 + tid])
                       + RSQP[192 + tid];
        __syncthreads();
    }

    const int row0 = wm * 16 + (lane >> 2);
    const int row1 = row0 + 8;
    const uint32_t lrow = lane & 15;
    const uint32_t acol = (uint32_t)((lane >> 4) << 4);
    const uint32_t a_row_off = (uint32_t)(wm * 16 + lrow) * 144u + acol;
    const uint32_t boff = lrow * RSTRB + acol
                        + (uint32_t)(wn * 4) * (16u * RSTRB);
    const float INF = __int_as_float(0x7f800000);

    #pragma unroll 1
    for (int l = 0; l < QL; ++l) {
        const __half* Bh0 = g_cbh + (size_t)l * KC * DD;

        for (int i = tid; i < KC; i += NTHR) csq_sm[i] = g_csq[l * KC + i];

        const float rsq0 = RSQ[row0];
        const float rsq1 = RSQ[row1];

        float a_v0 = INF, a_v1 = INF, a_v2 = INF, a_v3 = INF;
        int   a_i0 = 0,   a_i1 = 0,   a_i2 = 0,   a_i3 = 0;
        float b_v0 = INF, b_v1 = INF, b_v2 = INF, b_v3 = INF;
        int   b_i0 = 0,   b_i1 = 0,   b_i2 = 0,   b_i3 = 0;
        float acc[8][4];

        auto issue = [&](int it) {
            const int ntb = (it >> 4) * NTL;
            const int d0  = (it & 15) * 32;
            const uint32_t st = sb + (uint32_t)(it % NSTG) * STG_SZ;
            #pragma unroll
            for (int i = 0; i < 2; ++i) {
                const int gi = i * 256 + tid;       // 512 granules
                const int r = gi >> 2, g = gi & 3;
                cpa16(st + (uint32_t)r * RSTRB + (uint32_t)g * 16u,
                      Bh0 + (size_t)(ntb + r) * DD + d0 + g * 8);
            }
        };

        issue(0); CP_COMMIT();
        issue(1); CP_COMMIT();

        #pragma unroll 1
        for (int it = 0; it < NITER; ++it) {
            if (it + 2 < NITER) { issue(it + 2); CP_COMMIT(); CP_WAIT2(); }
            else if (it + 1 < NITER) { CP_WAIT1(); }
            else { CP_WAIT0(); }
            __syncthreads();

            if ((it & 15) == 0) {
                #pragma unroll
                for (int t = 0; t < 8; ++t)
                    #pragma unroll
                    for (int k = 0; k < 4; ++k) acc[t][k] = 0.f;
            }

            const int chunk = it & 15;
            const uint32_t abase = sb + OF_A + (uint32_t)(chunk >> 1) * ASC_SZ
                                   + (uint32_t)(chunk & 1) * 64u + a_row_off;
            const uint32_t stage = sb + (uint32_t)(it % NSTG) * STG_SZ;
            #pragma unroll
            for (int ks = 0; ks < 2; ++ks) {
                uint32_t a0, a1, a2, a3;
                LDSM4(a0, a1, a2, a3, abase + (uint32_t)ks * 32u);
                #pragma unroll
                for (int cg = 0; cg < 4; ++cg) {
                    const uint32_t bo = boff + (uint32_t)cg * (16u * RSTRB)
                                             + (uint32_t)ks * 32u;
                    uint32_t b0, b1, b2, b3;
                    LDSM4(b0, b1, b2, b3, stage + bo);
                    // n-group0 uses (m0, m2); group1 (m1, m3)
                    MMA_FP16(acc[cg * 2],     a0, a1, a2, a3, b0, b2);
                    MMA_FP16(acc[cg * 2 + 1], a0, a1, a2, a3, b1, b3);
                }
            }

            if ((it & 15) == 15) {
                const int ntb = (it >> 4) * NTL + wn * 64;
                #pragma unroll
                for (int nt = 0; nt < 8; ++nt) {
                    int c0 = ntb + nt * 8 + 2 * (lane & 3);
                    float q0 = csq_sm[c0], q1 = csq_sm[c0 + 1];
                    float d00 = fmaf(-2.f, acc[nt][0], rsq0) + q0;
                    float d01 = fmaf(-2.f, acc[nt][1], rsq0) + q1;
                    float d10 = fmaf(-2.f, acc[nt][2], rsq1) + q0;
                    float d11 = fmaf(-2.f, acc[nt][3], rsq1) + q1;
                    TOP4_INS(a_v0,a_i0,a_v1,a_i1,a_v2,a_i2,a_v3,a_i3, d00, c0);
                    TOP4_INS(a_v0,a_i0,a_v1,a_i1,a_v2,a_i2,a_v3,a_i3, d01, c0 + 1);
                    TOP4_INS(b_v0,b_i0,b_v1,b_i1,b_v2,b_i2,b_v3,b_i3, d10, c0);
                    TOP4_INS(b_v0,b_i0,b_v1,b_i1,b_v2,b_i2,b_v3,b_i3, d11, c0 + 1);
                }
            }
            __syncthreads();
        }

        // ---- publish candidates (stage region dead)
        float* CV = (float*)(sm + OF_CV);
        int*   CI = (int*)(sm + OF_CI);
        {
            const int s0 = (wn * 4 + (lane & 3)) * 4;
            int b0 = row0 * NCAND + s0;
            CV[b0]     = a_v0; CI[b0]     = a_i0;
            CV[b0 + 1] = a_v1; CI[b0 + 1] = a_i1;
            CV[b0 + 2] = a_v2; CI[b0 + 2] = a_i2;
            CV[b0 + 3] = a_v3; CI[b0 + 3] = a_i3;
            int b1 = row1 * NCAND + s0;
            CV[b1]     = b_v0; CI[b1]     = b_i0;
            CV[b1 + 1] = b_v1; CI[b1 + 1] = b_i1;
            CV[b1 + 2] = b_v2; CI[b1 + 2] = b_i2;
            CV[b1 + 3] = b_v3; CI[b1 + 3] = b_i3;
        }
        __syncthreads();

        // ---- phase 2
        int*   SEL  = (int*)(sm + OF_SEL);
        float* DOTP = (float*)(sm + OF_DOTP);
        int*   WIDX = (int*)(sm + OF_WIDX);
        float* RSQP = (float*)(sm + OF_RSQP);

        if (tsub == 0) {
            #pragma unroll 1
            for (int s = 0; s < NRES; ++s) {
                float bv = CV[tloc * NCAND]; int bi = CI[tloc * NCAND]; int bp = 0;
                #pragma unroll 1
                for (int j = 1; j < NCAND; ++j) {
                    float v = CV[tloc * NCAND + j]; int ii = CI[tloc * NCAND + j];
                    if (v < bv || (v == bv && ii < bi)) { bv = v; bi = ii; bp = j; }
                }
                SEL[tloc * NRES + s] = bi;
                CV[tloc * NCAND + bp] = INF;
            }
        }
        __syncthreads();

        const float* rp = (l == 0 ? x : g_res) + (size_t)tok * DD + dbase;

        // exact fp32 rescore of NRES candidates (sequential fmaf, proven chain)
        {
            const float* bp[NRES];
            float p[NRES];
            #pragma unroll
            for (int c = 0; c < NRES; ++c) {
                bp[c] = cb + ((size_t)l * KC + SEL[tloc * NRES + c]) * DD + dbase;
                p[c] = 0.f;
            }
            #pragma unroll 2
            for (int j = 0; j < 128; j += 4) {
                float4 r = *(const float4*)(rp + j);
                #pragma unroll
                for (int c = 0; c < NRES; ++c) {
                    float4 b = *(const float4*)(bp[c] + j);
                    p[c] = fmaf(r.x, b.x, p[c]); p[c] = fmaf(r.y, b.y, p[c]);
                    p[c] = fmaf(r.z, b.z, p[c]); p[c] = fmaf(r.w, b.w, p[c]);
                }
            }
            #pragma unroll
            for (int c = 0; c < NRES; ++c)
                DOTP[c * 256 + tsub * 64 + tloc] = p[c];
        }
        __syncthreads();
        if (tsub == 0) {
            float rq = RSQ[tloc];
            float bd = INF; int bi = 0x7fffffff;
            #pragma unroll
            for (int c = 0; c < NRES; ++c) {
                int code = SEL[tloc * NRES + c];
                float dot = ((DOTP[c * 256 + tloc] + DOTP[c * 256 + 64 + tloc])
                             + DOTP[c * 256 + 128 + tloc])
                            + DOTP[c * 256 + 192 + tloc];
                float d = fmaf(-2.f, dot, rq) + csq_sm[code];
                if (d < bd || (d == bd && code < bi)) { bd = d; bi = code; }
            }
            WIDX[tloc] = bi;
            out[IDXOFF + (size_t)tok * QL + l] = (float)bi;
            atomicAdd(&g_cnt[l * KC + bi], 1);
        }
        __syncthreads();

        const int idx = WIDX[tloc];
        const float* qv = cb + ((size_t)l * KC + idx) * DD + dbase;
        float* rw = g_res + (size_t)tok * DD + dbase;
        const float* xp = x + (size_t)tok * DD + dbase;
        float* op = out + (size_t)tok * DD + dbase;

        float s = 0.f;
        #pragma unroll 4
        for (int j = 0; j < 128; j += 4) {
            float4 r = *(const float4*)(rp + j);
            float4 q = *(const float4*)(qv + j);
            float rn[4] = {r.x - q.x, r.y - q.y, r.z - q.z, r.w - q.w};
            s += rn[0] * rn[0]; s += rn[1] * rn[1];
            s += rn[2] * rn[2]; s += rn[3] * rn[3];
            if (l < QL - 1) {
                *(float4*)(rw + j) = make_float4(rn[0], rn[1], rn[2], rn[3]);
                char* ap = sm + OF_A + (uint32_t)(tsub * 2 + (j >> 6)) * ASC_SZ
                           + (uint32_t)tloc * 144u + (uint32_t)(j & 63) * 2u;
                *(__half2*)ap       = __floats2half2_rn(rn[0], rn[1]);
                *(__half2*)(ap + 4) = __floats2half2_rn(rn[2], rn[3]);
            } else {
                float4 xv = *(const float4*)(xp + j);
                float qs0 = xv.x - rn[0], qs1 = xv.y - rn[1];
                float qs2 = xv.z - rn[2], qs3 = xv.w - rn[3];
                float4 ov;
                ov.x = xv.x + (qs0 - xv.x);
                ov.y = xv.y + (qs1 - xv.y);
                ov.z = xv.z + (qs2 - xv.z);
                ov.w = xv.w + (qs3 - xv.w);
                *(float4*)(op + j) = ov;
            }
        }
        RSQP[tsub * 64 + tloc] = s;
        __syncthreads();
        if (tid < 64)
            RSQ[tid] = ((RSQP[tid] + RSQP[64 + tid]) + RSQP[128 + tid])
                       + RSQP[192 + tid];
        __syncthreads();
        if (tid == 0) {
            double cs = 0.0;
            for (int t = 0; t < MTOK; ++t) cs += (double)RSQ[t];
            atomicAdd(&g_commit[l], cs);
        }
        __syncthreads();
    }
}

// ---------------------------------------------------------------------------
__global__ void rvq_fin(float* __restrict__ out) {
    __shared__ double red[256];
    const int tid = threadIdx.x;
    double psum = 0.0;
    for (int l = 0; l < QL; ++l) {
        double s = 0.0;
        for (int k = tid; k < KC; k += 256) {
            double p = (double)g_cnt[l * KC + k] / (double)NTOK;
            s += p * log(p + 1e-10);
        }
        red[tid] = s;
        __syncthreads();
        for (int off = 128; off > 0; off >>= 1) {
            if (tid < off) red[tid] += red[tid + off];
            __syncthreads();
        }
        if (tid == 0) psum += exp(-red[0]);
        __syncthreads();
    }
    if (tid == 0) {
        double closs = 0.0;
        for (int l = 0; l < QL; ++l)
            closs += g_commit[l] / ((double)NTOK * (double)DD);
        out[SCLOFF]     = (float)(0.25 * closs);
        out[SCLOFF + 1] = (float)(psum / (double)QL);
    }
}

// ---------------------------------------------------------------------------
extern "C" void kernel_launch(void* const* d_in, const int* in_sizes, int n_in,
                              void* d_out, int out_size) {
    const float* x  = (const float*)d_in[0];
    const float* cb = (const float*)d_in[1];
    float* out = (float*)d_out;

    cudaFuncSetAttribute(rvq_persist,
                         cudaFuncAttributeMaxDynamicSharedMemorySize, SMEM_TOT);

    rvq_prep<<<QL * KC / 64, 256>>>(cb);
    rvq_cbconv<<<(int)(((size_t)QL * KC * DD / 4 + 255) / 256), 256>>>(cb);
    rvq_persist<<<NTOK / MTOK, NTHR, SMEM_TOT>>>(x, cb, out);
    rvq_fin<<<1, 256>>>(out);
}